// round 13
// baseline (speedup 1.0000x reference)
#include <cuda_runtime.h>
#include <cuda_fp16.h>
#include <cstdint>

#define BB 256
#define NN 256
#define IND 64
#define HID 128
#define NOUT 16
#define NL 3
#define NK 4
#define MM (BB*NN)
#define LN_EPS 1e-5f
#define EP 136
#define EPB (EP*2)

__device__ uint16_t g_yhi[(size_t)MM * HID];
__device__ uint16_t g_ylo[(size_t)MM * HID];
__device__ uint16_t g_fhi[(size_t)MM * IND];
__device__ uint16_t g_flo[(size_t)MM * IND];
__device__ uint16_t g_ewh[(size_t)NK * HID * HID];
__device__ uint16_t g_nwh[(size_t)NL * HID * HID];
__device__ uint16_t g_nwl[(size_t)NL * HID * HID];
__device__ float    g_ebsum[HID];

__device__ __forceinline__ void splith(float a, uint16_t &h, uint16_t &l) {
    __half hh = __float2half_rn(a);
    __half ll = __float2half_rn(a - __half2float(hh));
    h = __half_as_ushort(hh); l = __half_as_ushort(ll);
}
__device__ __forceinline__ uint32_t packu(uint16_t a, uint16_t b) {
    return (uint32_t)a | ((uint32_t)b << 16);
}
__device__ __forceinline__ uint32_t f22h2(float x, float y) {
    __half2 h = __floats2half2_rn(x, y);
    return *(uint32_t*)&h;
}
__device__ __forceinline__ float2 h2pairf(uint32_t hbits, uint32_t lbits) {
    float2 a = __half22float2(*(__half2*)&hbits);
    float2 b = __half22float2(*(__half2*)&lbits);
    return make_float2(a.x + b.x, a.y + b.y);
}
__device__ __forceinline__ uint32_t cvta_s(const void* p) {
    return (uint32_t)__cvta_generic_to_shared(p);
}
__device__ __forceinline__ void ldsm_x4(uint32_t* r, uint32_t addr) {
    asm volatile("ldmatrix.sync.aligned.m8n8.x4.shared.b16 {%0,%1,%2,%3}, [%4];"
                 : "=r"(r[0]), "=r"(r[1]), "=r"(r[2]), "=r"(r[3]) : "r"(addr));
}
__device__ __forceinline__ void ldsm_x4_t(uint32_t* r, uint32_t addr) {
    asm volatile("ldmatrix.sync.aligned.m8n8.x4.trans.shared.b16 {%0,%1,%2,%3}, [%4];"
                 : "=r"(r[0]), "=r"(r[1]), "=r"(r[2]), "=r"(r[3]) : "r"(addr));
}
__device__ __forceinline__ void mma_f16(float* c, const uint32_t* a, const uint32_t* b) {
    asm volatile("mma.sync.aligned.m16n8k16.row.col.f32.f16.f16.f32 "
                 "{%0,%1,%2,%3}, {%4,%5,%6,%7}, {%8,%9}, {%0,%1,%2,%3};"
                 : "+f"(c[0]), "+f"(c[1]), "+f"(c[2]), "+f"(c[3])
                 : "r"(a[0]), "r"(a[1]), "r"(a[2]), "r"(a[3]), "r"(b[0]), "r"(b[1]));
}
__device__ __forceinline__ void cp16(uint32_t dst, const void* src) {
    asm volatile("cp.async.cg.shared.global [%0], [%1], 16;" :: "r"(dst), "l"(src));
}
#define CP_COMMIT() asm volatile("cp.async.commit_group;")
#define CP_WAIT(n)  asm volatile("cp.async.wait_group %0;" :: "n"(n))

// ---------------------------------------------------------------------------------------
__global__ void prep_weights(const float* __restrict__ nW0, const float* __restrict__ nW1,
                             const float* __restrict__ nW2, const float* __restrict__ eW,
                             uint16_t* __restrict__ nwh, uint16_t* __restrict__ nwl,
                             uint16_t* __restrict__ ewh)
{
    const int bid = blockIdx.x, tid = threadIdx.x;
    if (bid < 32) {
        const int idx = bid * 256 + tid;
        const int o = idx >> 6, d = idx & 63;
        uint16_t h, l; splith(nW0[idx], h, l);
        nwh[d * 128 + o] = h; nwl[d * 128 + o] = l;
    } else if (bid < 96) {
        const int idx = (bid - 32) * 256 + tid;
        const int o = idx >> 7, d = idx & 127;
        uint16_t h, l; splith(nW1[idx], h, l);
        nwh[16384 + d * 128 + o] = h; nwl[16384 + d * 128 + o] = l;
    } else if (bid < 160) {
        const int idx = (bid - 96) * 256 + tid;
        const int o = idx >> 7, d = idx & 127;
        uint16_t h, l; splith(nW2[idx], h, l);
        nwh[32768 + d * 128 + o] = h; nwl[32768 + d * 128 + o] = l;
    } else {
        const int idx = (bid - 160) * 256 + tid;
        const int k = idx >> 14, rem = idx & 16383;
        const int o = rem >> 7, d = rem & 127;
        ewh[(k << 14) + d * 128 + o] = __half_as_ushort(__float2half_rn(eW[idx]));
    }
}

__global__ void prep_feat(const float* __restrict__ f, uint16_t* __restrict__ hi,
                          uint16_t* __restrict__ lo)
{
    const int idx = blockIdx.x * 256 + threadIdx.x;
    uint16_t h, l;
    splith(f[idx], h, l);
    hi[idx] = h; lo[idx] = l;
}

__global__ void prep_ebsum(const float* __restrict__ eb, float* __restrict__ ebsum)
{
    const int h = threadIdx.x;
    ebsum[h] = eb[h] + eb[HID + h] + eb[2*HID + h] + eb[3*HID + h];
}

// ---------------------------------------------------------------------------------------
// Layer-0 node linear (fp16 3-product). Unchanged, validated.
// ---------------------------------------------------------------------------------------
__global__ __launch_bounds__(256, 1) void lin_mma(
    const uint16_t* __restrict__ xhi, const uint16_t* __restrict__ xlo,
    const uint16_t* __restrict__ wh, const uint16_t* __restrict__ wl,
    const float* __restrict__ bias,
    uint16_t* __restrict__ Yhi, uint16_t* __restrict__ Ylo, int D)
{
    extern __shared__ __align__(16) uint16_t lsm[];
    const uint32_t aX  = cvta_s(lsm);
    const uint32_t pX  = 128 * EPB;
    const uint32_t aW  = aX + 2 * 128 * EPB;
    const uint32_t pW  = 128 * EPB;

    const int m0 = blockIdx.x * 128;
    const int tid = threadIdx.x, warp = tid >> 5, lane = tid & 31;
    const int rT = tid >> 4, cT = tid & 15;
    const uint32_t lds_off = (lane & 15) * EPB + ((lane >> 4) << 4);

    const int dch = D >> 3;
    #pragma unroll
    for (int q = 0; q < 8; q++) {
        const int row = q * 16 + rT;
        if (cT < dch) {
            const size_t gi = (size_t)(m0 + row) * D + cT * 8;
            cp16(aX + row * EPB + cT * 16, xhi + gi);
            cp16(aX + pX + row * EPB + cT * 16, xlo + gi);
        }
    }
    for (int q = 0; q < (D >> 4); q++) {
        const int row = q * 16 + rT;
        const size_t gi = (size_t)row * 128 + cT * 8;
        cp16(aW + row * EPB + cT * 16, wh + gi);
        cp16(aW + pW + row * EPB + cT * 16, wl + gi);
    }
    CP_COMMIT(); CP_WAIT(0); __syncthreads();

    float macc[16][4];
    #pragma unroll
    for (int j = 0; j < 16; j++)
        #pragma unroll
        for (int t = 0; t < 4; t++) macc[j][t] = 0.f;

    for (int dc = 0; dc < (D >> 4); dc++) {
        uint32_t ah[4], al[4];
        const uint32_t axo = aX + (warp * 16 + (lane & 15)) * EPB + dc * 32 + ((lane >> 4) << 4);
        ldsm_x4(ah, axo);
        ldsm_x4(al, axo + pX);
        const uint32_t wb = aW + dc * 16 * EPB + lds_off;
        #pragma unroll
        for (int jj = 0; jj < 8; jj++) {
            uint32_t bh[4], bl[4];
            ldsm_x4_t(bh, wb + jj * 32);
            ldsm_x4_t(bl, wb + pW + jj * 32);
            #pragma unroll
            for (int tp = 0; tp < 2; tp++) {
                mma_f16(macc[2*jj+tp], ah, &bh[2*tp]);
                mma_f16(macc[2*jj+tp], ah, &bl[2*tp]);
                mma_f16(macc[2*jj+tp], al, &bh[2*tp]);
            }
        }
    }

    const int r0 = m0 + warp * 16 + (lane >> 2);
    #pragma unroll
    for (int j = 0; j < 16; j++) {
        const int col = j * 8 + (lane & 3) * 2;
        const float2 bb = *(const float2*)&bias[col];
        const float v0 = macc[j][0] + bb.x, v1 = macc[j][1] + bb.y;
        const float v2 = macc[j][2] + bb.x, v3 = macc[j][3] + bb.y;
        const size_t o0 = (size_t)r0 * HID + col;
        const size_t o1 = o0 + 8 * HID;
        uint16_t h0,l0,h1,l1;
        splith(v0,h0,l0); splith(v1,h1,l1);
        ((uint32_t*)Yhi)[o0 >> 1] = packu(h0,h1);
        ((uint32_t*)Ylo)[o0 >> 1] = packu(l0,l1);
        splith(v2,h0,l0); splith(v3,h1,l1);
        ((uint32_t*)Yhi)[o1 >> 1] = packu(h0,h1);
        ((uint32_t*)Ylo)[o1 >> 1] = packu(l0,l1);
    }
}

// ---------------------------------------------------------------------------------------
// Persistent per-graph kernel: 3 MP layers (2 half-passes each) + readout.
// smem: YH0(256xEP) | YH1(256xEP) | WB0(128xEP) | WB1(128xEP) = 208896 B.
// y-hi ping-pongs in smem across layers; y-lo residual via gmem (row-local, L2-hot).
// ---------------------------------------------------------------------------------------
__global__ __launch_bounds__(256, 1) void persist(
    const float* __restrict__ adj, const uint16_t* __restrict__ y0hi,
    uint16_t* __restrict__ ylo_g, const uint16_t* __restrict__ wThi,
    const float* __restrict__ ebsum, const float* __restrict__ lng,
    const float* __restrict__ lnb,
    const uint16_t* __restrict__ nwh, const uint16_t* __restrict__ nwl,
    const float* __restrict__ nb1, const float* __restrict__ nb2,
    const float* __restrict__ oW, const float* __restrict__ ob,
    float* __restrict__ out)
{
    extern __shared__ __align__(16) uint16_t dsm[];
    __shared__ float repr[HID];
    const uint32_t base = cvta_s(dsm);
    const uint32_t WB0 = base + 512 * EPB;
    const uint32_t WB1 = WB0 + 128 * EPB;

    const int b = blockIdx.x;
    const int tid = threadIdx.x, warp = tid >> 5, lane = tid & 31;
    const int rT = tid >> 4, cT = tid & 15;
    const int ar = lane >> 2, ac = (lane & 3) * 2;
    const uint32_t lds_off = (lane & 15) * EPB + ((lane >> 4) << 4);

    if (tid < HID) repr[tid] = 0.f;

    // stage layer-0 y hi planes into YH0
    #pragma unroll
    for (int q = 0; q < 16; q++) {
        const int row = q * 16 + rT;
        cp16(base + row * EPB + cT * 16, y0hi + ((size_t)b * NN + row) * HID + cT * 8);
    }
    CP_COMMIT();

    float2 adjP[2][4];
#define ADJ_LD(BUF_, KK_, MCC_, WR_) do {                                                \
    const float* An_ = adj + (((size_t)(b * NK + (KK_)) * NN + (WR_)) * NN) + (MCC_)*16; \
    adjP[BUF_][0] = *(const float2*)(An_ + (size_t)ar * NN + ac);                        \
    adjP[BUF_][1] = *(const float2*)(An_ + (size_t)(ar+8) * NN + ac);                    \
    adjP[BUF_][2] = *(const float2*)(An_ + (size_t)ar * NN + ac + 8);                    \
    adjP[BUF_][3] = *(const float2*)(An_ + (size_t)(ar+8) * NN + ac + 8);                \
} while(0)

    for (int layer = 0; layer < NL; layer++) {
        const uint32_t ycur = (layer & 1) ? 256u * EPB : 0u;      // byte offset in dsm
        const uint32_t ynxt = (layer & 1) ? 0u : 256u * EPB;
        const float* lg = lng + layer * HID;
        const float* lb = lnb + layer * HID;
        const int last = (layer == NL - 1);

        for (int pass = 0; pass < 2; pass++) {
            const int wrow = pass * 128 + warp * 16;

            // stage edge W0 -> WB0, W1 -> WB1 (separate groups)
            #pragma unroll
            for (int q = 0; q < 8; q++) {
                const int row = q * 16 + rT;
                cp16(WB0 + row * EPB + cT * 16, wThi + (size_t)row * 128 + cT * 8);
            }
            CP_COMMIT();
            #pragma unroll
            for (int q = 0; q < 8; q++) {
                const int row = q * 16 + rT;
                cp16(WB1 + row * EPB + cT * 16, wThi + 16384 + (size_t)row * 128 + cT * 8);
            }
            CP_COMMIT();
            ADJ_LD(0, 0, 0, wrow);
            ADJ_LD(1, 0, 1, wrow);

            float macc[16][4];
            #pragma unroll
            for (int j = 0; j < 16; j++)
                #pragma unroll
                for (int t = 0; t < 4; t++) macc[j][t] = 0.f;

            for (int k = 0; k < NK; k++) {
                float nacc[16][4];
                #pragma unroll
                for (int j = 0; j < 16; j++)
                    #pragma unroll
                    for (int t = 0; t < 4; t++) nacc[j][t] = 0.f;

                #pragma unroll
                for (int mc = 0; mc < 16; mc++) {
                    uint32_t ah[4];
                    #pragma unroll
                    for (int q = 0; q < 4; q++)
                        ah[q] = f22h2(adjP[mc&1][q].x, adjP[mc&1][q].y);
                    if (mc < 14) {
                        ADJ_LD(mc&1, k, mc + 2, wrow);
                    } else if (k < NK - 1) {
                        ADJ_LD(mc&1, k + 1, mc - 14, wrow);
                    }
                    const uint32_t yb = base + ycur + mc * 16 * EPB + lds_off;
                    #pragma unroll
                    for (int jj = 0; jj < 8; jj++) {
                        uint32_t bh[4];
                        ldsm_x4_t(bh, yb + jj * 32);
                        mma_f16(nacc[2*jj],   ah, &bh[0]);
                        mma_f16(nacc[2*jj+1], ah, &bh[2]);
                    }
                }

                if (k < NK - 1) { CP_WAIT(1); } else { CP_WAIT(0); }
                __syncthreads();

                const uint32_t wslot = (k & 1) ? WB1 : WB0;
                #pragma unroll
                for (int hc = 0; hc < 8; hc++) {
                    uint32_t ah[4];
                    ah[0] = f22h2(nacc[2*hc][0],   nacc[2*hc][1]);
                    ah[1] = f22h2(nacc[2*hc][2],   nacc[2*hc][3]);
                    ah[2] = f22h2(nacc[2*hc+1][0], nacc[2*hc+1][1]);
                    ah[3] = f22h2(nacc[2*hc+1][2], nacc[2*hc+1][3]);
                    const uint32_t wb = wslot + hc * 16 * EPB + lds_off;
                    #pragma unroll
                    for (int jj = 0; jj < 8; jj++) {
                        uint32_t bh[4];
                        ldsm_x4_t(bh, wb + jj * 32);
                        mma_f16(macc[2*jj],   ah, &bh[0]);
                        mma_f16(macc[2*jj+1], ah, &bh[2]);
                    }
                }
                __syncthreads();
                if (k < NK - 2) {
                    const uint32_t dst = (k & 1) ? WB1 : WB0;
                    #pragma unroll
                    for (int q = 0; q < 8; q++) {
                        const int row = q * 16 + rT;
                        cp16(dst + row * EPB + cT * 16,
                             wThi + ((size_t)(k + 2) << 14) + (size_t)row * 128 + cT * 8);
                    }
                    CP_COMMIT();
                }
            }

            // stage node W[layer+1] into WB (freed) — overlaps LN epilogue
            if (!last) {
                const uint16_t* wn_h = nwh + 16384 * (layer + 1);
                const uint16_t* wn_l = nwl + 16384 * (layer + 1);
                #pragma unroll
                for (int q = 0; q < 8; q++) {
                    const int row = q * 16 + rT;
                    cp16(WB0 + row * EPB + cT * 16, wn_h + (size_t)row * 128 + cT * 8);
                    cp16(WB1 + row * EPB + cT * 16, wn_l + (size_t)row * 128 + cT * 8);
                }
                CP_COMMIT();
            }

            // LN epilogue: residual = smem y-hi + gmem y-lo
            const int r0 = wrow + (lane >> 2);
            const int r1 = r0 + 8;
            const uint32_t* yl32 = (const uint32_t*)ylo_g;
            float s0 = 0.f, q0 = 0.f, s1 = 0.f, q1 = 0.f;
            #pragma unroll
            for (int j = 0; j < 16; j++) {
                const int col = j * 8 + (lane & 3) * 2;
                const float2 e = *(const float2*)&ebsum[col];
                const size_t w0 = ((size_t)b * NN + r0) * HID + col;
                const size_t w1 = ((size_t)b * NN + r1) * HID + col;
                const uint32_t h0b = *(const uint32_t*)((const char*)dsm + ycur + r0 * EPB + col * 2);
                const uint32_t h1b = *(const uint32_t*)((const char*)dsm + ycur + r1 * EPB + col * 2);
                const float2 y0 = h2pairf(h0b, yl32[w0 >> 1]);
                const float2 y1 = h2pairf(h1b, yl32[w1 >> 1]);
                macc[j][0] += y0.x + e.x;  macc[j][1] += y0.y + e.y;
                macc[j][2] += y1.x + e.x;  macc[j][3] += y1.y + e.y;
                s0 += macc[j][0] + macc[j][1];
                q0 += macc[j][0]*macc[j][0] + macc[j][1]*macc[j][1];
                s1 += macc[j][2] + macc[j][3];
                q1 += macc[j][2]*macc[j][2] + macc[j][3]*macc[j][3];
            }
            #pragma unroll
            for (int d = 1; d <= 2; d <<= 1) {
                s0 += __shfl_xor_sync(0xffffffffu, s0, d);
                q0 += __shfl_xor_sync(0xffffffffu, q0, d);
                s1 += __shfl_xor_sync(0xffffffffu, s1, d);
                q1 += __shfl_xor_sync(0xffffffffu, q1, d);
            }
            const float mu0 = s0 * (1.f/HID), mu1 = s1 * (1.f/HID);
            const float ri0 = rsqrtf(q0 * (1.f/HID) - mu0*mu0 + LN_EPS);
            const float ri1 = rsqrtf(q1 * (1.f/HID) - mu1*mu1 + LN_EPS);
            #pragma unroll
            for (int j = 0; j < 16; j++) {
                const int col = j * 8 + (lane & 3) * 2;
                const float2 gg = *(const float2*)&lg[col];
                const float2 bbv = *(const float2*)&lb[col];
                macc[j][0] = fmaxf((macc[j][0]-mu0)*ri0*gg.x + bbv.x, 0.f);
                macc[j][1] = fmaxf((macc[j][1]-mu0)*ri0*gg.y + bbv.y, 0.f);
                macc[j][2] = fmaxf((macc[j][2]-mu1)*ri1*gg.x + bbv.x, 0.f);
                macc[j][3] = fmaxf((macc[j][3]-mu1)*ri1*gg.y + bbv.y, 0.f);
            }

            if (last) {
                // readout accumulation
                #pragma unroll
                for (int j = 0; j < 16; j++) {
                    const int col = j * 8 + (lane & 3) * 2;
                    atomicAdd(&repr[col],     macc[j][0] + macc[j][2]);
                    atomicAdd(&repr[col + 1], macc[j][1] + macc[j][3]);
                }
            } else {
                CP_WAIT(0); __syncthreads();   // Wnode resident
                const float* nbias = (layer == 0) ? nb1 : nb2;
                float yacc[16][4];
                #pragma unroll
                for (int j = 0; j < 16; j++)
                    #pragma unroll
                    for (int t = 0; t < 4; t++) yacc[j][t] = 0.f;
                #pragma unroll
                for (int kc = 0; kc < 8; kc++) {
                    uint32_t ahh[4], ahl[4];
                    uint16_t h0,l0,h1,l1;
                    splith(macc[2*kc][0],h0,l0);   splith(macc[2*kc][1],h1,l1);
                    ahh[0]=packu(h0,h1); ahl[0]=packu(l0,l1);
                    splith(macc[2*kc][2],h0,l0);   splith(macc[2*kc][3],h1,l1);
                    ahh[1]=packu(h0,h1); ahl[1]=packu(l0,l1);
                    splith(macc[2*kc+1][0],h0,l0); splith(macc[2*kc+1][1],h1,l1);
                    ahh[2]=packu(h0,h1); ahl[2]=packu(l0,l1);
                    splith(macc[2*kc+1][2],h0,l0); splith(macc[2*kc+1][3],h1,l1);
                    ahh[3]=packu(h0,h1); ahl[3]=packu(l0,l1);
                    const uint32_t wb = WB0 + kc * 16 * EPB + lds_off;
                    #pragma unroll
                    for (int jj = 0; jj < 8; jj++) {
                        uint32_t bh[4], bl[4];
                        ldsm_x4_t(bh, wb + jj * 32);
                        ldsm_x4_t(bl, (wb + (WB1 - WB0)) + jj * 32);
                        #pragma unroll
                        for (int tp = 0; tp < 2; tp++) {
                            mma_f16(yacc[2*jj+tp], ahh, &bh[2*tp]);
                            mma_f16(yacc[2*jj+tp], ahh, &bl[2*tp]);
                            mma_f16(yacc[2*jj+tp], ahl, &bh[2*tp]);
                        }
                    }
                }
                // write y' hi -> smem (next layer buffer), lo -> gmem
                #pragma unroll
                for (int j = 0; j < 16; j++) {
                    const int col = j * 8 + (lane & 3) * 2;
                    const float2 bbv = *(const float2*)&nbias[col];
                    const float v0 = yacc[j][0] + bbv.x, v1 = yacc[j][1] + bbv.y;
                    const float v2 = yacc[j][2] + bbv.x, v3 = yacc[j][3] + bbv.y;
                    const size_t w0 = ((size_t)b * NN + r0) * HID + col;
                    const size_t w1 = ((size_t)b * NN + r1) * HID + col;
                    uint16_t h0,l0,h1,l1;
                    splith(v0,h0,l0); splith(v1,h1,l1);
                    *(uint32_t*)((char*)dsm + ynxt + r0 * EPB + col * 2) = packu(h0,h1);
                    ((uint32_t*)ylo_g)[w0 >> 1] = packu(l0,l1);
                    splith(v2,h0,l0); splith(v3,h1,l1);
                    *(uint32_t*)((char*)dsm + ynxt + r1 * EPB + col * 2) = packu(h0,h1);
                    ((uint32_t*)ylo_g)[w1 >> 1] = packu(l0,l1);
                }
            }
            __syncthreads();   // protect WB reuse + ynxt visibility
        }
    }

    // readout: out[b,:] = repr @ oW^T + ob
    if (tid < NOUT) {
        float acc = ob[tid];
        #pragma unroll 8
        for (int d = 0; d < HID; d++) acc += repr[d] * oW[tid * HID + d];
        out[b * NOUT + tid] = acc;
    }
#undef ADJ_LD
}

// ---------------------------------------------------------------------------------------
extern "C" void kernel_launch(void* const* d_in, const int* in_sizes, int n_in,
                              void* d_out, int out_size)
{
    const float* feat = (const float*)d_in[0];
    const float* adj  = (const float*)d_in[1];
    const float* nW[3] = {(const float*)d_in[2], (const float*)d_in[4], (const float*)d_in[6]};
    const float* nb[3] = {(const float*)d_in[3], (const float*)d_in[5], (const float*)d_in[7]};
    const float* eW  = (const float*)d_in[8];
    const float* ebp = (const float*)d_in[9];
    const float* lng = (const float*)d_in[10];
    const float* lnb = (const float*)d_in[11];
    const float* oW  = (const float*)d_in[12];
    const float* ob  = (const float*)d_in[13];

    float *ebs;
    uint16_t *yAh, *yAl, *fhi, *flo, *ewh, *nwh, *nwl;
    cudaGetSymbolAddress((void**)&yAh, g_yhi);
    cudaGetSymbolAddress((void**)&yAl, g_ylo);
    cudaGetSymbolAddress((void**)&fhi, g_fhi);
    cudaGetSymbolAddress((void**)&flo, g_flo);
    cudaGetSymbolAddress((void**)&ewh, g_ewh);
    cudaGetSymbolAddress((void**)&nwh, g_nwh);
    cudaGetSymbolAddress((void**)&nwl, g_nwl);
    cudaGetSymbolAddress((void**)&ebs, g_ebsum);

    const int PERSIST_SMEM = (512 + 256) * EPB;   // 208896 B
    const int LIN_SMEM     = 4 * 128 * EPB;       // 139264 B
    cudaFuncSetAttribute(persist, cudaFuncAttributeMaxDynamicSharedMemorySize, PERSIST_SMEM);
    cudaFuncSetAttribute(lin_mma, cudaFuncAttributeMaxDynamicSharedMemorySize, LIN_SMEM);

    prep_weights<<<416, 256>>>(nW[0], nW[1], nW[2], eW, nwh, nwl, ewh);
    prep_feat<<<MM*IND/256, 256>>>(feat, fhi, flo);
    prep_ebsum<<<1, HID>>>(ebp, ebs);

    lin_mma<<<MM/128, 256, LIN_SMEM>>>(fhi, flo, nwh, nwl, nb[0], yAh, yAl, IND);
    persist<<<BB, 256, PERSIST_SMEM>>>(adj, yAh, yAl, ewh, ebs, lng, lnb,
                                       nwh, nwl, nb[1], nb[2], oW, ob, (float*)d_out);
}

// round 14
// speedup vs baseline: 1.2001x; 1.2001x over previous
#include <cuda_runtime.h>
#include <cuda_fp16.h>
#include <cstdint>

#define BB 256
#define NN 256
#define IND 64
#define HID 128
#define NOUT 16
#define NL 3
#define NK 4
#define MM (BB*NN)
#define LN_EPS 1e-5f
#define EP 136
#define EPB (EP*2)

__device__ uint16_t g_yhi[(size_t)MM * HID];
__device__ uint16_t g_ylo[(size_t)MM * HID];
__device__ uint16_t g_xhi[(size_t)MM * HID];
__device__ uint16_t g_xlo[(size_t)MM * HID];
__device__ float    g_x[(size_t)MM * HID];
__device__ uint16_t g_fhi[(size_t)MM * IND];
__device__ uint16_t g_flo[(size_t)MM * IND];
__device__ uint16_t g_ewh[(size_t)NK * HID * HID];
__device__ uint16_t g_nwh[(size_t)NL * HID * HID];
__device__ uint16_t g_nwl[(size_t)NL * HID * HID];
__device__ float    g_ebsum[HID];

__device__ __forceinline__ void splith(float a, uint16_t &h, uint16_t &l) {
    __half hh = __float2half_rn(a);
    __half ll = __float2half_rn(a - __half2float(hh));
    h = __half_as_ushort(hh); l = __half_as_ushort(ll);
}
__device__ __forceinline__ uint32_t packu(uint16_t a, uint16_t b) {
    return (uint32_t)a | ((uint32_t)b << 16);
}
__device__ __forceinline__ uint32_t f22h2(float x, float y) {
    __half2 h = __floats2half2_rn(x, y);
    return *(uint32_t*)&h;
}
__device__ __forceinline__ float2 h2pairf(uint32_t hbits, uint32_t lbits) {
    float2 a = __half22float2(*(__half2*)&hbits);
    float2 b = __half22float2(*(__half2*)&lbits);
    return make_float2(a.x + b.x, a.y + b.y);
}
__device__ __forceinline__ uint32_t cvta_s(const void* p) {
    return (uint32_t)__cvta_generic_to_shared(p);
}
__device__ __forceinline__ void ldsm_x4(uint32_t* r, uint32_t addr) {
    asm volatile("ldmatrix.sync.aligned.m8n8.x4.shared.b16 {%0,%1,%2,%3}, [%4];"
                 : "=r"(r[0]), "=r"(r[1]), "=r"(r[2]), "=r"(r[3]) : "r"(addr));
}
__device__ __forceinline__ void ldsm_x4_t(uint32_t* r, uint32_t addr) {
    asm volatile("ldmatrix.sync.aligned.m8n8.x4.trans.shared.b16 {%0,%1,%2,%3}, [%4];"
                 : "=r"(r[0]), "=r"(r[1]), "=r"(r[2]), "=r"(r[3]) : "r"(addr));
}
__device__ __forceinline__ void mma_f16(float* c, const uint32_t* a, const uint32_t* b) {
    asm volatile("mma.sync.aligned.m16n8k16.row.col.f32.f16.f16.f32 "
                 "{%0,%1,%2,%3}, {%4,%5,%6,%7}, {%8,%9}, {%0,%1,%2,%3};"
                 : "+f"(c[0]), "+f"(c[1]), "+f"(c[2]), "+f"(c[3])
                 : "r"(a[0]), "r"(a[1]), "r"(a[2]), "r"(a[3]), "r"(b[0]), "r"(b[1]));
}
__device__ __forceinline__ void cp16(uint32_t dst, const void* src) {
    asm volatile("cp.async.cg.shared.global [%0], [%1], 16;" :: "r"(dst), "l"(src));
}
#define CP_COMMIT() asm volatile("cp.async.commit_group;")
#define CP_WAIT(n)  asm volatile("cp.async.wait_group %0;" :: "n"(n))

// ---------------------------------------------------------------------------------------
__global__ void prep_weights(const float* __restrict__ nW0, const float* __restrict__ nW1,
                             const float* __restrict__ nW2, const float* __restrict__ eW,
                             uint16_t* __restrict__ nwh, uint16_t* __restrict__ nwl,
                             uint16_t* __restrict__ ewh)
{
    const int bid = blockIdx.x, tid = threadIdx.x;
    if (bid < 32) {
        const int idx = bid * 256 + tid;
        const int o = idx >> 6, d = idx & 63;
        uint16_t h, l; splith(nW0[idx], h, l);
        nwh[d * 128 + o] = h; nwl[d * 128 + o] = l;
    } else if (bid < 96) {
        const int idx = (bid - 32) * 256 + tid;
        const int o = idx >> 7, d = idx & 127;
        uint16_t h, l; splith(nW1[idx], h, l);
        nwh[16384 + d * 128 + o] = h; nwl[16384 + d * 128 + o] = l;
    } else if (bid < 160) {
        const int idx = (bid - 96) * 256 + tid;
        const int o = idx >> 7, d = idx & 127;
        uint16_t h, l; splith(nW2[idx], h, l);
        nwh[32768 + d * 128 + o] = h; nwl[32768 + d * 128 + o] = l;
    } else {
        const int idx = (bid - 160) * 256 + tid;
        const int k = idx >> 14, rem = idx & 16383;
        const int o = rem >> 7, d = rem & 127;
        ewh[(k << 14) + d * 128 + o] = __half_as_ushort(__float2half_rn(eW[idx]));
    }
}

__global__ void prep_feat(const float* __restrict__ f, uint16_t* __restrict__ hi,
                          uint16_t* __restrict__ lo)
{
    const int idx = blockIdx.x * 256 + threadIdx.x;
    uint16_t h, l;
    splith(f[idx], h, l);
    hi[idx] = h; lo[idx] = l;
}

__global__ void prep_ebsum(const float* __restrict__ eb, float* __restrict__ ebsum)
{
    const int h = threadIdx.x;
    ebsum[h] = eb[h] + eb[HID + h] + eb[2*HID + h] + eb[3*HID + h];
}

// ---------------------------------------------------------------------------------------
// Layer-0 node linear: 64-row blocks, 128 threads, 2 CTAs/SM. Per-warp code unchanged.
// ---------------------------------------------------------------------------------------
__global__ __launch_bounds__(128, 2) void lin_mma(
    const uint16_t* __restrict__ xhi, const uint16_t* __restrict__ xlo,
    const uint16_t* __restrict__ wh, const uint16_t* __restrict__ wl,
    const float* __restrict__ bias,
    uint16_t* __restrict__ Yhi, uint16_t* __restrict__ Ylo, int D)
{
    extern __shared__ __align__(16) uint16_t lsm[];
    const uint32_t aX  = cvta_s(lsm);                 // 64 x EP hi
    const uint32_t pX  = 64 * EPB;                    // lo plane offset
    const uint32_t aW  = aX + 2 * 64 * EPB;           // D(=64) x EP hi
    const uint32_t pW  = 64 * EPB;

    const int m0 = blockIdx.x * 64;
    const int tid = threadIdx.x, warp = tid >> 5, lane = tid & 31;
    const int rT = tid >> 4, cT = tid & 15;           // rT 0..7
    const uint32_t lds_off = (lane & 15) * EPB + ((lane >> 4) << 4);

    const int dch = D >> 3;                           // 8 chunks per X row
    #pragma unroll
    for (int q = 0; q < 8; q++) {
        const int row = q * 8 + rT;                   // 0..63
        if (cT < dch) {
            const size_t gi = (size_t)(m0 + row) * D + cT * 8;
            cp16(aX + row * EPB + cT * 16, xhi + gi);
            cp16(aX + pX + row * EPB + cT * 16, xlo + gi);
        }
    }
    #pragma unroll
    for (int q = 0; q < 8; q++) {
        const int row = q * 8 + rT;                   // 0..63 (= D rows)
        const size_t gi = (size_t)row * 128 + cT * 8;
        cp16(aW + row * EPB + cT * 16, wh + gi);
        cp16(aW + pW + row * EPB + cT * 16, wl + gi);
    }
    CP_COMMIT(); CP_WAIT(0); __syncthreads();

    float macc[16][4];
    #pragma unroll
    for (int j = 0; j < 16; j++)
        #pragma unroll
        for (int t = 0; t < 4; t++) macc[j][t] = 0.f;

    for (int dc = 0; dc < (D >> 4); dc++) {
        uint32_t ah[4], al[4];
        const uint32_t axo = aX + (warp * 16 + (lane & 15)) * EPB + dc * 32 + ((lane >> 4) << 4);
        ldsm_x4(ah, axo);
        ldsm_x4(al, axo + pX);
        const uint32_t wb = aW + dc * 16 * EPB + lds_off;
        #pragma unroll
        for (int jj = 0; jj < 8; jj++) {
            uint32_t bh[4], bl[4];
            ldsm_x4_t(bh, wb + jj * 32);
            ldsm_x4_t(bl, wb + pW + jj * 32);
            #pragma unroll
            for (int tp = 0; tp < 2; tp++) {
                mma_f16(macc[2*jj+tp], ah, &bh[2*tp]);
                mma_f16(macc[2*jj+tp], ah, &bl[2*tp]);
                mma_f16(macc[2*jj+tp], al, &bh[2*tp]);
            }
        }
    }

    const int r0 = m0 + warp * 16 + (lane >> 2);
    #pragma unroll
    for (int j = 0; j < 16; j++) {
        const int col = j * 8 + (lane & 3) * 2;
        const float2 bb = *(const float2*)&bias[col];
        const float v0 = macc[j][0] + bb.x, v1 = macc[j][1] + bb.y;
        const float v2 = macc[j][2] + bb.x, v3 = macc[j][3] + bb.y;
        const size_t o0 = (size_t)r0 * HID + col;
        const size_t o1 = o0 + 8 * HID;
        uint16_t h0,l0,h1,l1;
        splith(v0,h0,l0); splith(v1,h1,l1);
        ((uint32_t*)Yhi)[o0 >> 1] = packu(h0,h1);
        ((uint32_t*)Ylo)[o0 >> 1] = packu(l0,l1);
        splith(v2,h0,l0); splith(v3,h1,l1);
        ((uint32_t*)Yhi)[o1 >> 1] = packu(h0,h1);
        ((uint32_t*)Ylo)[o1 >> 1] = packu(l0,l1);
    }
}

// ---------------------------------------------------------------------------------------
// Fused MP + LN + ReLU + (mode 0) next-layer node linear.
// 64-row blocks, 128 threads, 104448 B smem -> 2 CTAs/SM. Single W buffer (R11 pattern).
// ---------------------------------------------------------------------------------------
__global__ __launch_bounds__(128, 2) void fused_mp(
    const float* __restrict__ adj, const uint16_t* __restrict__ yhi,
    const uint16_t* __restrict__ ylo, const uint16_t* __restrict__ wThi,
    const float* __restrict__ ebsum, const float* __restrict__ lng,
    const float* __restrict__ lnb,
    const uint16_t* __restrict__ wnh, const uint16_t* __restrict__ wnl,
    const float* __restrict__ nbias,
    uint16_t* __restrict__ youth, uint16_t* __restrict__ youtl,
    float* __restrict__ xout, int mode)
{
    extern __shared__ __align__(16) uint16_t dsm[];
    const uint32_t aY = cvta_s(dsm);                 // 256 x EP (y hi; later Wnode hi+lo)
    const uint32_t aW = aY + 256 * EPB;              // 128 x EP (edge W[k] hi)
    const uint32_t pN = 128 * EPB;                   // Wnode lo offset within aY region

    const int b = blockIdx.y;
    const int n0 = blockIdx.x * 64;
    const int tid = threadIdx.x, warp = tid >> 5, lane = tid & 31;
    const int wrow = n0 + warp * 16;
    const int rT = tid >> 4, cT = tid & 15;          // rT 0..7
    const int ar = lane >> 2, ac = (lane & 3) * 2;
    const uint32_t lds_off = (lane & 15) * EPB + ((lane >> 4) << 4);

    float2 adjP[2][4];
#define ADJ_LD(BUF_, KK_, MCC_) do {                                                     \
    const float* An_ = adj + (((size_t)(b * NK + (KK_)) * NN + wrow) * NN) + (MCC_) * 16;\
    adjP[BUF_][0] = *(const float2*)(An_ + (size_t)ar * NN + ac);                        \
    adjP[BUF_][1] = *(const float2*)(An_ + (size_t)(ar+8) * NN + ac);                    \
    adjP[BUF_][2] = *(const float2*)(An_ + (size_t)ar * NN + ac + 8);                    \
    adjP[BUF_][3] = *(const float2*)(An_ + (size_t)(ar+8) * NN + ac + 8);                \
} while(0)

    // stage y hi (256 rows) + W[0] (128 rows)
    #pragma unroll
    for (int q = 0; q < 32; q++) {
        const int row = q * 8 + rT;                  // 0..255
        cp16(aY + row * EPB + cT * 16, yhi + ((size_t)b * NN + row) * HID + cT * 8);
    }
    #pragma unroll
    for (int q = 0; q < 16; q++) {
        const int row = q * 8 + rT;                  // 0..127
        cp16(aW + row * EPB + cT * 16, wThi + (size_t)row * 128 + cT * 8);
    }
    CP_COMMIT();
    ADJ_LD(0, 0, 0);
    ADJ_LD(1, 0, 1);
    CP_WAIT(0); __syncthreads();

    float macc[16][4];
    #pragma unroll
    for (int j = 0; j < 16; j++)
        #pragma unroll
        for (int t = 0; t < 4; t++) macc[j][t] = 0.f;

    for (int k = 0; k < NK; k++) {
        float nacc[16][4];
        #pragma unroll
        for (int j = 0; j < 16; j++)
            #pragma unroll
            for (int t = 0; t < 4; t++) nacc[j][t] = 0.f;

        #pragma unroll
        for (int mc = 0; mc < 16; mc++) {
            uint32_t ah[4];
            #pragma unroll
            for (int q = 0; q < 4; q++)
                ah[q] = f22h2(adjP[mc&1][q].x, adjP[mc&1][q].y);
            if (mc < 14) {
                ADJ_LD(mc&1, k, mc + 2);
            } else if (k < NK - 1) {
                ADJ_LD(mc&1, k + 1, mc - 14);
            }
            const uint32_t yb = aY + mc * 16 * EPB + lds_off;
            #pragma unroll
            for (int jj = 0; jj < 8; jj++) {
                uint32_t bh[4];
                ldsm_x4_t(bh, yb + jj * 32);
                mma_f16(nacc[2*jj],   ah, &bh[0]);
                mma_f16(nacc[2*jj+1], ah, &bh[2]);
            }
        }

        CP_WAIT(0); __syncthreads();   // W[k] resident

        // at last k, aY dead -> stage Wnode (overlaps GEMM2 + LN)
        if (k == NK - 1 && mode == 0) {
            #pragma unroll
            for (int q = 0; q < 16; q++) {
                const int row = q * 8 + rT;
                cp16(aY + row * EPB + cT * 16,      wnh + (size_t)row * 128 + cT * 8);
                cp16(aY + pN + row * EPB + cT * 16, wnl + (size_t)row * 128 + cT * 8);
            }
            CP_COMMIT();
        }

        #pragma unroll
        for (int hc = 0; hc < 8; hc++) {
            uint32_t ah[4];
            ah[0] = f22h2(nacc[2*hc][0],   nacc[2*hc][1]);
            ah[1] = f22h2(nacc[2*hc][2],   nacc[2*hc][3]);
            ah[2] = f22h2(nacc[2*hc+1][0], nacc[2*hc+1][1]);
            ah[3] = f22h2(nacc[2*hc+1][2], nacc[2*hc+1][3]);
            const uint32_t wb = aW + hc * 16 * EPB + lds_off;
            #pragma unroll
            for (int jj = 0; jj < 8; jj++) {
                uint32_t bh[4];
                ldsm_x4_t(bh, wb + jj * 32);
                mma_f16(macc[2*jj],   ah, &bh[0]);
                mma_f16(macc[2*jj+1], ah, &bh[2]);
            }
        }
        __syncthreads();               // all warps done reading aW
        if (k < NK - 1) {
            #pragma unroll
            for (int q = 0; q < 16; q++) {
                const int row = q * 8 + rT;
                cp16(aW + row * EPB + cT * 16,
                     wThi + ((size_t)(k + 1) << 14) + (size_t)row * 128 + cT * 8);
            }
            CP_COMMIT();
        }
    }

    // -------- epilogue: residual + ebsum + LN + ReLU (x kept in macc) --------
    const int r0 = wrow + (lane >> 2);
    const int r1 = r0 + 8;
    const uint32_t* yh32 = (const uint32_t*)yhi;
    const uint32_t* yl32 = (const uint32_t*)ylo;
    float s0 = 0.f, q0 = 0.f, s1 = 0.f, q1 = 0.f;
    #pragma unroll
    for (int j = 0; j < 16; j++) {
        const int col = j * 8 + (lane & 3) * 2;
        const float2 e = *(const float2*)&ebsum[col];
        const size_t w0 = ((size_t)b * NN + r0) * HID + col;
        const size_t w1 = ((size_t)b * NN + r1) * HID + col;
        const float2 y0 = h2pairf(yh32[w0 >> 1], yl32[w0 >> 1]);
        const float2 y1 = h2pairf(yh32[w1 >> 1], yl32[w1 >> 1]);
        macc[j][0] += y0.x + e.x;  macc[j][1] += y0.y + e.y;
        macc[j][2] += y1.x + e.x;  macc[j][3] += y1.y + e.y;
        s0 += macc[j][0] + macc[j][1];
        q0 += macc[j][0]*macc[j][0] + macc[j][1]*macc[j][1];
        s1 += macc[j][2] + macc[j][3];
        q1 += macc[j][2]*macc[j][2] + macc[j][3]*macc[j][3];
    }
    #pragma unroll
    for (int d = 1; d <= 2; d <<= 1) {
        s0 += __shfl_xor_sync(0xffffffffu, s0, d);
        q0 += __shfl_xor_sync(0xffffffffu, q0, d);
        s1 += __shfl_xor_sync(0xffffffffu, s1, d);
        q1 += __shfl_xor_sync(0xffffffffu, q1, d);
    }
    const float mu0 = s0 * (1.f/HID), mu1 = s1 * (1.f/HID);
    const float ri0 = rsqrtf(q0 * (1.f/HID) - mu0*mu0 + LN_EPS);
    const float ri1 = rsqrtf(q1 * (1.f/HID) - mu1*mu1 + LN_EPS);

    #pragma unroll
    for (int j = 0; j < 16; j++) {
        const int col = j * 8 + (lane & 3) * 2;
        const float2 gg = *(const float2*)&lng[col];
        const float2 bb = *(const float2*)&lnb[col];
        macc[j][0] = fmaxf((macc[j][0]-mu0)*ri0*gg.x + bb.x, 0.f);
        macc[j][1] = fmaxf((macc[j][1]-mu0)*ri0*gg.y + bb.y, 0.f);
        macc[j][2] = fmaxf((macc[j][2]-mu1)*ri1*gg.x + bb.x, 0.f);
        macc[j][3] = fmaxf((macc[j][3]-mu1)*ri1*gg.y + bb.y, 0.f);
    }

    if (mode == 1) {
        #pragma unroll
        for (int j = 0; j < 16; j++) {
            const int col = j * 8 + (lane & 3) * 2;
            const size_t w0 = ((size_t)b * NN + r0) * HID + col;
            *(float2*)&xout[w0] = make_float2(macc[j][0], macc[j][1]);
            *(float2*)&xout[w0 + 8 * HID] = make_float2(macc[j][2], macc[j][3]);
        }
        return;
    }

    // -------- GEMM3: y' = x @ Wnode^T + b (3-product, x split in-register) --------
    CP_WAIT(0); __syncthreads();       // Wnode planes resident in aY region

    float yacc[16][4];
    #pragma unroll
    for (int j = 0; j < 16; j++)
        #pragma unroll
        for (int t = 0; t < 4; t++) yacc[j][t] = 0.f;

    #pragma unroll
    for (int kc = 0; kc < 8; kc++) {
        uint32_t ahh[4], ahl[4];
        uint16_t h0,l0,h1,l1;
        splith(macc[2*kc][0],h0,l0);   splith(macc[2*kc][1],h1,l1);
        ahh[0]=packu(h0,h1); ahl[0]=packu(l0,l1);
        splith(macc[2*kc][2],h0,l0);   splith(macc[2*kc][3],h1,l1);
        ahh[1]=packu(h0,h1); ahl[1]=packu(l0,l1);
        splith(macc[2*kc+1][0],h0,l0); splith(macc[2*kc+1][1],h1,l1);
        ahh[2]=packu(h0,h1); ahl[2]=packu(l0,l1);
        splith(macc[2*kc+1][2],h0,l0); splith(macc[2*kc+1][3],h1,l1);
        ahh[3]=packu(h0,h1); ahl[3]=packu(l0,l1);
        const uint32_t wb = aY + kc * 16 * EPB + lds_off;
        #pragma unroll
        for (int jj = 0; jj < 8; jj++) {
            uint32_t bh[4], bl[4];
            ldsm_x4_t(bh, wb + jj * 32);
            ldsm_x4_t(bl, wb + pN + jj * 32);
            #pragma unroll
            for (int tp = 0; tp < 2; tp++) {
                mma_f16(yacc[2*jj+tp], ahh, &bh[2*tp]);
                mma_f16(yacc[2*jj+tp], ahh, &bl[2*tp]);
                mma_f16(yacc[2*jj+tp], ahl, &bh[2*tp]);
            }
        }
    }

    #pragma unroll
    for (int j = 0; j < 16; j++) {
        const int col = j * 8 + (lane & 3) * 2;
        const float2 bb = *(const float2*)&nbias[col];
        const float v0 = yacc[j][0] + bb.x, v1 = yacc[j][1] + bb.y;
        const float v2 = yacc[j][2] + bb.x, v3 = yacc[j][3] + bb.y;
        const size_t w0 = ((size_t)b * NN + r0) * HID + col;
        const size_t w1 = ((size_t)b * NN + r1) * HID + col;
        uint16_t h0,l0,h1,l1;
        splith(v0,h0,l0); splith(v1,h1,l1);
        ((uint32_t*)youth)[w0 >> 1] = packu(h0,h1);
        ((uint32_t*)youtl)[w0 >> 1] = packu(l0,l1);
        splith(v2,h0,l0); splith(v3,h1,l1);
        ((uint32_t*)youth)[w1 >> 1] = packu(h0,h1);
        ((uint32_t*)youtl)[w1 >> 1] = packu(l0,l1);
    }
#undef ADJ_LD
}

// ---------------------------------------------------------------------------------------
__global__ void readout_kernel(const float* __restrict__ x, const float* __restrict__ oW,
                               const float* __restrict__ ob, float* __restrict__ out)
{
    const int b = blockIdx.x;
    const int tid = threadIdx.x;
    const int half = tid >> 7;
    const int c4 = (tid & 127) >> 2;
    const int rr = tid & 3;
    float4 s = make_float4(0.f, 0.f, 0.f, 0.f);
    const float* xp = x + ((size_t)b * NN + half * 128) * HID + c4 * 4;
    #pragma unroll 4
    for (int n = rr; n < 128; n += 4) {
        const float4 v = *(const float4*)(xp + (size_t)n * HID);
        s.x += v.x; s.y += v.y; s.z += v.z; s.w += v.w;
    }
    __shared__ float repr[HID];
    if (tid < HID) repr[tid] = 0.f;
    __syncthreads();
    atomicAdd(&repr[c4 * 4 + 0], s.x);
    atomicAdd(&repr[c4 * 4 + 1], s.y);
    atomicAdd(&repr[c4 * 4 + 2], s.z);
    atomicAdd(&repr[c4 * 4 + 3], s.w);
    __syncthreads();
    if (tid < NOUT) {
        float acc = ob[tid];
        #pragma unroll 8
        for (int d = 0; d < HID; d++) acc += repr[d] * oW[tid * HID + d];
        out[b * NOUT + tid] = acc;
    }
}

// ---------------------------------------------------------------------------------------
extern "C" void kernel_launch(void* const* d_in, const int* in_sizes, int n_in,
                              void* d_out, int out_size)
{
    const float* feat = (const float*)d_in[0];
    const float* adj  = (const float*)d_in[1];
    const float* nW[3] = {(const float*)d_in[2], (const float*)d_in[4], (const float*)d_in[6]};
    const float* nb[3] = {(const float*)d_in[3], (const float*)d_in[5], (const float*)d_in[7]};
    const float* eW  = (const float*)d_in[8];
    const float* ebp = (const float*)d_in[9];
    const float* lng = (const float*)d_in[10];
    const float* lnb = (const float*)d_in[11];
    const float* oW  = (const float*)d_in[12];
    const float* ob  = (const float*)d_in[13];

    float *xb, *ebs;
    uint16_t *yAh, *yAl, *yBh, *yBl, *fhi, *flo, *ewh, *nwh, *nwl;
    cudaGetSymbolAddress((void**)&yAh, g_yhi);
    cudaGetSymbolAddress((void**)&yAl, g_ylo);
    cudaGetSymbolAddress((void**)&yBh, g_xhi);
    cudaGetSymbolAddress((void**)&yBl, g_xlo);
    cudaGetSymbolAddress((void**)&xb,  g_x);
    cudaGetSymbolAddress((void**)&fhi, g_fhi);
    cudaGetSymbolAddress((void**)&flo, g_flo);
    cudaGetSymbolAddress((void**)&ewh, g_ewh);
    cudaGetSymbolAddress((void**)&nwh, g_nwh);
    cudaGetSymbolAddress((void**)&nwl, g_nwl);
    cudaGetSymbolAddress((void**)&ebs, g_ebsum);

    const int FUSED_SMEM = (256 + 128) * EPB;   // 104448 B -> 2 CTAs/SM
    const int LIN_SMEM   = 4 * 64 * EPB;        // 69632 B  -> 2 CTAs/SM
    cudaFuncSetAttribute(fused_mp, cudaFuncAttributeMaxDynamicSharedMemorySize, FUSED_SMEM);
    cudaFuncSetAttribute(lin_mma,  cudaFuncAttributeMaxDynamicSharedMemorySize, LIN_SMEM);

    prep_weights<<<416, 256>>>(nW[0], nW[1], nW[2], eW, nwh, nwl, ewh);
    prep_feat<<<MM*IND/256, 256>>>(feat, fhi, flo);
    prep_ebsum<<<1, HID>>>(ebp, ebs);

    // layer 0 node linear: feat -> yA
    lin_mma<<<MM/64, 128, LIN_SMEM>>>(fhi, flo, nwh, nwl, nb[0], yAh, yAl, IND);
    // layer 0 MP (+node linear for layer 1): yA -> yB
    fused_mp<<<dim3(4, BB), 128, FUSED_SMEM>>>(adj, yAh, yAl, ewh, ebs,
                                               lng, lnb,
                                               nwh + 16384, nwl + 16384, nb[1],
                                               yBh, yBl, xb, 0);
    // layer 1 MP (+node linear for layer 2): yB -> yA   <-- profiled launch
    fused_mp<<<dim3(4, BB), 128, FUSED_SMEM>>>(adj, yBh, yBl, ewh, ebs,
                                               lng + HID, lnb + HID,
                                               nwh + 32768, nwl + 32768, nb[2],
                                               yAh, yAl, xb, 0);
    // layer 2 MP -> fp32 x
    fused_mp<<<dim3(4, BB), 128, FUSED_SMEM>>>(adj, yAh, yAl, ewh, ebs,
                                               lng + 2*HID, lnb + 2*HID,
                                               nwh, nwl, nb[0],
                                               yBh, yBl, xb, 1);
    readout_kernel<<<BB, 256>>>(xb, oW, ob, (float*)d_out);
}

// round 15
// speedup vs baseline: 1.2246x; 1.0204x over previous
#include <cuda_runtime.h>
#include <cuda_fp16.h>
#include <cstdint>

#define BB 256
#define NN 256
#define IND 64
#define HID 128
#define NOUT 16
#define NL 3
#define NK 4
#define MM (BB*NN)
#define LN_EPS 1e-5f
#define EP 136
#define EPB (EP*2)

__device__ uint16_t g_yhi[(size_t)MM * HID];
__device__ uint16_t g_ylo[(size_t)MM * HID];
__device__ uint16_t g_xhi[(size_t)MM * HID];
__device__ uint16_t g_xlo[(size_t)MM * HID];
__device__ uint16_t g_fhi[(size_t)MM * IND];
__device__ uint16_t g_flo[(size_t)MM * IND];
__device__ uint16_t g_ewh[(size_t)NK * HID * HID];
__device__ uint16_t g_nwh[(size_t)NL * HID * HID];
__device__ uint16_t g_nwl[(size_t)NL * HID * HID];
__device__ float    g_ebsum[HID];
__device__ float    g_repr[(size_t)BB * HID];

__device__ __forceinline__ void splith(float a, uint16_t &h, uint16_t &l) {
    __half hh = __float2half_rn(a);
    __half ll = __float2half_rn(a - __half2float(hh));
    h = __half_as_ushort(hh); l = __half_as_ushort(ll);
}
__device__ __forceinline__ uint32_t packu(uint16_t a, uint16_t b) {
    return (uint32_t)a | ((uint32_t)b << 16);
}
__device__ __forceinline__ uint32_t f22h2(float x, float y) {
    __half2 h = __floats2half2_rn(x, y);
    return *(uint32_t*)&h;
}
__device__ __forceinline__ float2 h2pairf(uint32_t hbits, uint32_t lbits) {
    float2 a = __half22float2(*(__half2*)&hbits);
    float2 b = __half22float2(*(__half2*)&lbits);
    return make_float2(a.x + b.x, a.y + b.y);
}
__device__ __forceinline__ uint32_t cvta_s(const void* p) {
    return (uint32_t)__cvta_generic_to_shared(p);
}
__device__ __forceinline__ void ldsm_x4(uint32_t* r, uint32_t addr) {
    asm volatile("ldmatrix.sync.aligned.m8n8.x4.shared.b16 {%0,%1,%2,%3}, [%4];"
                 : "=r"(r[0]), "=r"(r[1]), "=r"(r[2]), "=r"(r[3]) : "r"(addr));
}
__device__ __forceinline__ void ldsm_x4_t(uint32_t* r, uint32_t addr) {
    asm volatile("ldmatrix.sync.aligned.m8n8.x4.trans.shared.b16 {%0,%1,%2,%3}, [%4];"
                 : "=r"(r[0]), "=r"(r[1]), "=r"(r[2]), "=r"(r[3]) : "r"(addr));
}
__device__ __forceinline__ void mma_f16(float* c, const uint32_t* a, const uint32_t* b) {
    asm volatile("mma.sync.aligned.m16n8k16.row.col.f32.f16.f16.f32 "
                 "{%0,%1,%2,%3}, {%4,%5,%6,%7}, {%8,%9}, {%0,%1,%2,%3};"
                 : "+f"(c[0]), "+f"(c[1]), "+f"(c[2]), "+f"(c[3])
                 : "r"(a[0]), "r"(a[1]), "r"(a[2]), "r"(a[3]), "r"(b[0]), "r"(b[1]));
}
__device__ __forceinline__ void cp16(uint32_t dst, const void* src) {
    asm volatile("cp.async.cg.shared.global [%0], [%1], 16;" :: "r"(dst), "l"(src));
}
#define CP_COMMIT() asm volatile("cp.async.commit_group;")
#define CP_WAIT(n)  asm volatile("cp.async.wait_group %0;" :: "n"(n))

// ---------------------------------------------------------------------------------------
__global__ void prep_weights(const float* __restrict__ nW0, const float* __restrict__ nW1,
                             const float* __restrict__ nW2, const float* __restrict__ eW,
                             uint16_t* __restrict__ nwh, uint16_t* __restrict__ nwl,
                             uint16_t* __restrict__ ewh)
{
    const int bid = blockIdx.x, tid = threadIdx.x;
    if (bid < 32) {
        const int idx = bid * 256 + tid;
        const int o = idx >> 6, d = idx & 63;
        uint16_t h, l; splith(nW0[idx], h, l);
        nwh[d * 128 + o] = h; nwl[d * 128 + o] = l;
    } else if (bid < 96) {
        const int idx = (bid - 32) * 256 + tid;
        const int o = idx >> 7, d = idx & 127;
        uint16_t h, l; splith(nW1[idx], h, l);
        nwh[16384 + d * 128 + o] = h; nwl[16384 + d * 128 + o] = l;
    } else if (bid < 160) {
        const int idx = (bid - 96) * 256 + tid;
        const int o = idx >> 7, d = idx & 127;
        uint16_t h, l; splith(nW2[idx], h, l);
        nwh[32768 + d * 128 + o] = h; nwl[32768 + d * 128 + o] = l;
    } else {
        const int idx = (bid - 160) * 256 + tid;
        const int k = idx >> 14, rem = idx & 16383;
        const int o = rem >> 7, d = rem & 127;
        ewh[(k << 14) + d * 128 + o] = __half_as_ushort(__float2half_rn(eW[idx]));
    }
}

__global__ void prep_feat(const float* __restrict__ f, uint16_t* __restrict__ hi,
                          uint16_t* __restrict__ lo)
{
    const int idx = blockIdx.x * 256 + threadIdx.x;
    uint16_t h, l;
    splith(f[idx], h, l);
    hi[idx] = h; lo[idx] = l;
}

// ebsum (block 0) + zero g_repr (blocks 1..128)
__global__ void prep_misc(const float* __restrict__ eb, float* __restrict__ ebsum,
                          float* __restrict__ repr)
{
    if (blockIdx.x == 0) {
        if (threadIdx.x < HID) {
            const int h = threadIdx.x;
            ebsum[h] = eb[h] + eb[HID + h] + eb[2*HID + h] + eb[3*HID + h];
        }
    } else {
        repr[(blockIdx.x - 1) * 256 + threadIdx.x] = 0.f;
    }
}

// ---------------------------------------------------------------------------------------
// Layer-0 node linear: 64-row blocks, 128 threads, 2 CTAs/SM. (R14-validated)
// ---------------------------------------------------------------------------------------
__global__ __launch_bounds__(128, 2) void lin_mma(
    const uint16_t* __restrict__ xhi, const uint16_t* __restrict__ xlo,
    const uint16_t* __restrict__ wh, const uint16_t* __restrict__ wl,
    const float* __restrict__ bias,
    uint16_t* __restrict__ Yhi, uint16_t* __restrict__ Ylo, int D)
{
    extern __shared__ __align__(16) uint16_t lsm[];
    const uint32_t aX  = cvta_s(lsm);
    const uint32_t pX  = 64 * EPB;
    const uint32_t aW  = aX + 2 * 64 * EPB;
    const uint32_t pW  = 64 * EPB;

    const int m0 = blockIdx.x * 64;
    const int tid = threadIdx.x, warp = tid >> 5, lane = tid & 31;
    const int rT = tid >> 4, cT = tid & 15;
    const uint32_t lds_off = (lane & 15) * EPB + ((lane >> 4) << 4);

    const int dch = D >> 3;
    #pragma unroll
    for (int q = 0; q < 8; q++) {
        const int row = q * 8 + rT;
        if (cT < dch) {
            const size_t gi = (size_t)(m0 + row) * D + cT * 8;
            cp16(aX + row * EPB + cT * 16, xhi + gi);
            cp16(aX + pX + row * EPB + cT * 16, xlo + gi);
        }
    }
    #pragma unroll
    for (int q = 0; q < 8; q++) {
        const int row = q * 8 + rT;
        const size_t gi = (size_t)row * 128 + cT * 8;
        cp16(aW + row * EPB + cT * 16, wh + gi);
        cp16(aW + pW + row * EPB + cT * 16, wl + gi);
    }
    CP_COMMIT(); CP_WAIT(0); __syncthreads();

    float macc[16][4];
    #pragma unroll
    for (int j = 0; j < 16; j++)
        #pragma unroll
        for (int t = 0; t < 4; t++) macc[j][t] = 0.f;

    for (int dc = 0; dc < (D >> 4); dc++) {
        uint32_t ah[4], al[4];
        const uint32_t axo = aX + (warp * 16 + (lane & 15)) * EPB + dc * 32 + ((lane >> 4) << 4);
        ldsm_x4(ah, axo);
        ldsm_x4(al, axo + pX);
        const uint32_t wb = aW + dc * 16 * EPB + lds_off;
        #pragma unroll
        for (int jj = 0; jj < 8; jj++) {
            uint32_t bh[4], bl[4];
            ldsm_x4_t(bh, wb + jj * 32);
            ldsm_x4_t(bl, wb + pW + jj * 32);
            #pragma unroll
            for (int tp = 0; tp < 2; tp++) {
                mma_f16(macc[2*jj+tp], ah, &bh[2*tp]);
                mma_f16(macc[2*jj+tp], ah, &bl[2*tp]);
                mma_f16(macc[2*jj+tp], al, &bh[2*tp]);
            }
        }
    }

    const int r0 = m0 + warp * 16 + (lane >> 2);
    #pragma unroll
    for (int j = 0; j < 16; j++) {
        const int col = j * 8 + (lane & 3) * 2;
        const float2 bb = *(const float2*)&bias[col];
        const float v0 = macc[j][0] + bb.x, v1 = macc[j][1] + bb.y;
        const float v2 = macc[j][2] + bb.x, v3 = macc[j][3] + bb.y;
        const size_t o0 = (size_t)r0 * HID + col;
        const size_t o1 = o0 + 8 * HID;
        uint16_t h0,l0,h1,l1;
        splith(v0,h0,l0); splith(v1,h1,l1);
        ((uint32_t*)Yhi)[o0 >> 1] = packu(h0,h1);
        ((uint32_t*)Ylo)[o0 >> 1] = packu(l0,l1);
        splith(v2,h0,l0); splith(v3,h1,l1);
        ((uint32_t*)Yhi)[o1 >> 1] = packu(h0,h1);
        ((uint32_t*)Ylo)[o1 >> 1] = packu(l0,l1);
    }
}

// ---------------------------------------------------------------------------------------
// Fused MP + LN + ReLU + (mode 0) next-layer node linear | (mode 1) readout accumulation.
// 64-row blocks, 128 threads, 104448 B smem -> 2 CTAs/SM.
// ---------------------------------------------------------------------------------------
__global__ __launch_bounds__(128, 2) void fused_mp(
    const float* __restrict__ adj, const uint16_t* __restrict__ yhi,
    const uint16_t* __restrict__ ylo, const uint16_t* __restrict__ wThi,
    const float* __restrict__ ebsum, const float* __restrict__ lng,
    const float* __restrict__ lnb,
    const uint16_t* __restrict__ wnh, const uint16_t* __restrict__ wnl,
    const float* __restrict__ nbias,
    uint16_t* __restrict__ youth, uint16_t* __restrict__ youtl,
    float* __restrict__ repr_g, int mode)
{
    extern __shared__ __align__(16) uint16_t dsm[];
    const uint32_t aY = cvta_s(dsm);
    const uint32_t aW = aY + 256 * EPB;
    const uint32_t pN = 128 * EPB;

    const int b = blockIdx.y;
    const int n0 = blockIdx.x * 64;
    const int tid = threadIdx.x, warp = tid >> 5, lane = tid & 31;
    const int wrow = n0 + warp * 16;
    const int rT = tid >> 4, cT = tid & 15;
    const int ar = lane >> 2, ac = (lane & 3) * 2;
    const uint32_t lds_off = (lane & 15) * EPB + ((lane >> 4) << 4);

    float2 adjP[2][4];
#define ADJ_LD(BUF_, KK_, MCC_) do {                                                     \
    const float* An_ = adj + (((size_t)(b * NK + (KK_)) * NN + wrow) * NN) + (MCC_) * 16;\
    adjP[BUF_][0] = *(const float2*)(An_ + (size_t)ar * NN + ac);                        \
    adjP[BUF_][1] = *(const float2*)(An_ + (size_t)(ar+8) * NN + ac);                    \
    adjP[BUF_][2] = *(const float2*)(An_ + (size_t)ar * NN + ac + 8);                    \
    adjP[BUF_][3] = *(const float2*)(An_ + (size_t)(ar+8) * NN + ac + 8);                \
} while(0)

    #pragma unroll
    for (int q = 0; q < 32; q++) {
        const int row = q * 8 + rT;
        cp16(aY + row * EPB + cT * 16, yhi + ((size_t)b * NN + row) * HID + cT * 8);
    }
    #pragma unroll
    for (int q = 0; q < 16; q++) {
        const int row = q * 8 + rT;
        cp16(aW + row * EPB + cT * 16, wThi + (size_t)row * 128 + cT * 8);
    }
    CP_COMMIT();
    ADJ_LD(0, 0, 0);
    ADJ_LD(1, 0, 1);
    CP_WAIT(0); __syncthreads();

    float macc[16][4];
    #pragma unroll
    for (int j = 0; j < 16; j++)
        #pragma unroll
        for (int t = 0; t < 4; t++) macc[j][t] = 0.f;

    for (int k = 0; k < NK; k++) {
        float nacc[16][4];
        #pragma unroll
        for (int j = 0; j < 16; j++)
            #pragma unroll
            for (int t = 0; t < 4; t++) nacc[j][t] = 0.f;

        #pragma unroll
        for (int mc = 0; mc < 16; mc++) {
            uint32_t ah[4];
            #pragma unroll
            for (int q = 0; q < 4; q++)
                ah[q] = f22h2(adjP[mc&1][q].x, adjP[mc&1][q].y);
            if (mc < 14) {
                ADJ_LD(mc&1, k, mc + 2);
            } else if (k < NK - 1) {
                ADJ_LD(mc&1, k + 1, mc - 14);
            }
            const uint32_t yb = aY + mc * 16 * EPB + lds_off;
            #pragma unroll
            for (int jj = 0; jj < 8; jj++) {
                uint32_t bh[4];
                ldsm_x4_t(bh, yb + jj * 32);
                mma_f16(nacc[2*jj],   ah, &bh[0]);
                mma_f16(nacc[2*jj+1], ah, &bh[2]);
            }
        }

        CP_WAIT(0); __syncthreads();

        if (k == NK - 1 && mode == 0) {
            #pragma unroll
            for (int q = 0; q < 16; q++) {
                const int row = q * 8 + rT;
                cp16(aY + row * EPB + cT * 16,      wnh + (size_t)row * 128 + cT * 8);
                cp16(aY + pN + row * EPB + cT * 16, wnl + (size_t)row * 128 + cT * 8);
            }
            CP_COMMIT();
        }

        #pragma unroll
        for (int hc = 0; hc < 8; hc++) {
            uint32_t ah[4];
            ah[0] = f22h2(nacc[2*hc][0],   nacc[2*hc][1]);
            ah[1] = f22h2(nacc[2*hc][2],   nacc[2*hc][3]);
            ah[2] = f22h2(nacc[2*hc+1][0], nacc[2*hc+1][1]);
            ah[3] = f22h2(nacc[2*hc+1][2], nacc[2*hc+1][3]);
            const uint32_t wb = aW + hc * 16 * EPB + lds_off;
            #pragma unroll
            for (int jj = 0; jj < 8; jj++) {
                uint32_t bh[4];
                ldsm_x4_t(bh, wb + jj * 32);
                mma_f16(macc[2*jj],   ah, &bh[0]);
                mma_f16(macc[2*jj+1], ah, &bh[2]);
            }
        }
        __syncthreads();
        if (k < NK - 1) {
            #pragma unroll
            for (int q = 0; q < 16; q++) {
                const int row = q * 8 + rT;
                cp16(aW + row * EPB + cT * 16,
                     wThi + ((size_t)(k + 1) << 14) + (size_t)row * 128 + cT * 8);
            }
            CP_COMMIT();
        }
    }

    // -------- epilogue: residual + ebsum + LN + ReLU --------
    const int r0 = wrow + (lane >> 2);
    const int r1 = r0 + 8;
    const uint32_t* yh32 = (const uint32_t*)yhi;
    const uint32_t* yl32 = (const uint32_t*)ylo;
    float s0 = 0.f, q0 = 0.f, s1 = 0.f, q1 = 0.f;
    #pragma unroll
    for (int j = 0; j < 16; j++) {
        const int col = j * 8 + (lane & 3) * 2;
        const float2 e = *(const float2*)&ebsum[col];
        const size_t w0 = ((size_t)b * NN + r0) * HID + col;
        const size_t w1 = ((size_t)b * NN + r1) * HID + col;
        const float2 y0 = h2pairf(yh32[w0 >> 1], yl32[w0 >> 1]);
        const float2 y1 = h2pairf(yh32[w1 >> 1], yl32[w1 >> 1]);
        macc[j][0] += y0.x + e.x;  macc[j][1] += y0.y + e.y;
        macc[j][2] += y1.x + e.x;  macc[j][3] += y1.y + e.y;
        s0 += macc[j][0] + macc[j][1];
        q0 += macc[j][0]*macc[j][0] + macc[j][1]*macc[j][1];
        s1 += macc[j][2] + macc[j][3];
        q1 += macc[j][2]*macc[j][2] + macc[j][3]*macc[j][3];
    }
    #pragma unroll
    for (int d = 1; d <= 2; d <<= 1) {
        s0 += __shfl_xor_sync(0xffffffffu, s0, d);
        q0 += __shfl_xor_sync(0xffffffffu, q0, d);
        s1 += __shfl_xor_sync(0xffffffffu, s1, d);
        q1 += __shfl_xor_sync(0xffffffffu, q1, d);
    }
    const float mu0 = s0 * (1.f/HID), mu1 = s1 * (1.f/HID);
    const float ri0 = rsqrtf(q0 * (1.f/HID) - mu0*mu0 + LN_EPS);
    const float ri1 = rsqrtf(q1 * (1.f/HID) - mu1*mu1 + LN_EPS);

    #pragma unroll
    for (int j = 0; j < 16; j++) {
        const int col = j * 8 + (lane & 3) * 2;
        const float2 gg = *(const float2*)&lng[col];
        const float2 bb = *(const float2*)&lnb[col];
        macc[j][0] = fmaxf((macc[j][0]-mu0)*ri0*gg.x + bb.x, 0.f);
        macc[j][1] = fmaxf((macc[j][1]-mu0)*ri0*gg.y + bb.y, 0.f);
        macc[j][2] = fmaxf((macc[j][2]-mu1)*ri1*gg.x + bb.x, 0.f);
        macc[j][3] = fmaxf((macc[j][3]-mu1)*ri1*gg.y + bb.y, 0.f);
    }

    if (mode == 1) {
        // readout accumulation: column sums over this warp's 16 rows, reduced
        // across the 8 row-quads by shuffle, then 8 atomics for lanes 0..3.
        #pragma unroll
        for (int j = 0; j < 16; j++) {
            float v0 = macc[j][0] + macc[j][2];
            float v1 = macc[j][1] + macc[j][3];
            #pragma unroll
            for (int d = 4; d <= 16; d <<= 1) {
                v0 += __shfl_down_sync(0xffffffffu, v0, d);
                v1 += __shfl_down_sync(0xffffffffu, v1, d);
            }
            if ((lane >> 2) == 0) {
                const int col = j * 8 + lane * 2;
                atomicAdd(&repr_g[b * HID + col],     v0);
                atomicAdd(&repr_g[b * HID + col + 1], v1);
            }
        }
        return;
    }

    // -------- GEMM3: y' = x @ Wnode^T + b (3-product, x split in-register) --------
    CP_WAIT(0); __syncthreads();

    float yacc[16][4];
    #pragma unroll
    for (int j = 0; j < 16; j++)
        #pragma unroll
        for (int t = 0; t < 4; t++) yacc[j][t] = 0.f;

    #pragma unroll
    for (int kc = 0; kc < 8; kc++) {
        uint32_t ahh[4], ahl[4];
        uint16_t h0,l0,h1,l1;
        splith(macc[2*kc][0],h0,l0);   splith(macc[2*kc][1],h1,l1);
        ahh[0]=packu(h0,h1); ahl[0]=packu(l0,l1);
        splith(macc[2*kc][2],h0,l0);   splith(macc[2*kc][3],h1,l1);
        ahh[1]=packu(h0,h1); ahl[1]=packu(l0,l1);
        splith(macc[2*kc+1][0],h0,l0); splith(macc[2*kc+1][1],h1,l1);
        ahh[2]=packu(h0,h1); ahl[2]=packu(l0,l1);
        splith(macc[2*kc+1][2],h0,l0); splith(macc[2*kc+1][3],h1,l1);
        ahh[3]=packu(h0,h1); ahl[3]=packu(l0,l1);
        const uint32_t wb = aY + kc * 16 * EPB + lds_off;
        #pragma unroll
        for (int jj = 0; jj < 8; jj++) {
            uint32_t bh[4], bl[4];
            ldsm_x4_t(bh, wb + jj * 32);
            ldsm_x4_t(bl, wb + pN + jj * 32);
            #pragma unroll
            for (int tp = 0; tp < 2; tp++) {
                mma_f16(yacc[2*jj+tp], ahh, &bh[2*tp]);
                mma_f16(yacc[2*jj+tp], ahh, &bl[2*tp]);
                mma_f16(yacc[2*jj+tp], ahl, &bh[2*tp]);
            }
        }
    }

    #pragma unroll
    for (int j = 0; j < 16; j++) {
        const int col = j * 8 + (lane & 3) * 2;
        const float2 bb = *(const float2*)&nbias[col];
        const float v0 = yacc[j][0] + bb.x, v1 = yacc[j][1] + bb.y;
        const float v2 = yacc[j][2] + bb.x, v3 = yacc[j][3] + bb.y;
        const size_t w0 = ((size_t)b * NN + r0) * HID + col;
        const size_t w1 = ((size_t)b * NN + r1) * HID + col;
        uint16_t h0,l0,h1,l1;
        splith(v0,h0,l0); splith(v1,h1,l1);
        ((uint32_t*)youth)[w0 >> 1] = packu(h0,h1);
        ((uint32_t*)youtl)[w0 >> 1] = packu(l0,l1);
        splith(v2,h0,l0); splith(v3,h1,l1);
        ((uint32_t*)youth)[w1 >> 1] = packu(h0,h1);
        ((uint32_t*)youtl)[w1 >> 1] = packu(l0,l1);
    }
#undef ADJ_LD
}

// ---------------------------------------------------------------------------------------
__global__ void out_gemv(const float* __restrict__ repr, const float* __restrict__ oW,
                         const float* __restrict__ ob, float* __restrict__ out)
{
    const int b = blockIdx.x;
    const int o = threadIdx.x;           // 16 threads
    float acc = ob[o];
    const float* rp = repr + (size_t)b * HID;
    #pragma unroll 8
    for (int d = 0; d < HID; d++) acc += rp[d] * oW[o * HID + d];
    out[b * NOUT + o] = acc;
}

// ---------------------------------------------------------------------------------------
extern "C" void kernel_launch(void* const* d_in, const int* in_sizes, int n_in,
                              void* d_out, int out_size)
{
    const float* feat = (const float*)d_in[0];
    const float* adj  = (const float*)d_in[1];
    const float* nW[3] = {(const float*)d_in[2], (const float*)d_in[4], (const float*)d_in[6]};
    const float* nb[3] = {(const float*)d_in[3], (const float*)d_in[5], (const float*)d_in[7]};
    const float* eW  = (const float*)d_in[8];
    const float* ebp = (const float*)d_in[9];
    const float* lng = (const float*)d_in[10];
    const float* lnb = (const float*)d_in[11];
    const float* oW  = (const float*)d_in[12];
    const float* ob  = (const float*)d_in[13];

    float *ebs, *repr;
    uint16_t *yAh, *yAl, *yBh, *yBl, *fhi, *flo, *ewh, *nwh, *nwl;
    cudaGetSymbolAddress((void**)&yAh, g_yhi);
    cudaGetSymbolAddress((void**)&yAl, g_ylo);
    cudaGetSymbolAddress((void**)&yBh, g_xhi);
    cudaGetSymbolAddress((void**)&yBl, g_xlo);
    cudaGetSymbolAddress((void**)&fhi, g_fhi);
    cudaGetSymbolAddress((void**)&flo, g_flo);
    cudaGetSymbolAddress((void**)&ewh, g_ewh);
    cudaGetSymbolAddress((void**)&nwh, g_nwh);
    cudaGetSymbolAddress((void**)&nwl, g_nwl);
    cudaGetSymbolAddress((void**)&ebs, g_ebsum);
    cudaGetSymbolAddress((void**)&repr, g_repr);

    const int FUSED_SMEM = (256 + 128) * EPB;   // 104448 B -> 2 CTAs/SM
    const int LIN_SMEM   = 4 * 64 * EPB;        // 69632 B  -> 2 CTAs/SM
    cudaFuncSetAttribute(fused_mp, cudaFuncAttributeMaxDynamicSharedMemorySize, FUSED_SMEM);
    cudaFuncSetAttribute(lin_mma,  cudaFuncAttributeMaxDynamicSharedMemorySize, LIN_SMEM);

    prep_weights<<<416, 256>>>(nW[0], nW[1], nW[2], eW, nwh, nwl, ewh);
    prep_feat<<<MM*IND/256, 256>>>(feat, fhi, flo);
    prep_misc<<<129, 256>>>(ebp, ebs, repr);

    // layer 0 node linear: feat -> yA
    lin_mma<<<MM/64, 128, LIN_SMEM>>>(fhi, flo, nwh, nwl, nb[0], yAh, yAl, IND);
    // layer 0 MP (+node linear for layer 1): yA -> yB
    fused_mp<<<dim3(4, BB), 128, FUSED_SMEM>>>(adj, yAh, yAl, ewh, ebs,
                                               lng, lnb,
                                               nwh + 16384, nwl + 16384, nb[1],
                                               yBh, yBl, repr, 0);
    // layer 1 MP (+node linear for layer 2): yB -> yA   <-- profiled launch
    fused_mp<<<dim3(4, BB), 128, FUSED_SMEM>>>(adj, yBh, yBl, ewh, ebs,
                                               lng + HID, lnb + HID,
                                               nwh + 32768, nwl + 32768, nb[2],
                                               yAh, yAl, repr, 0);
    // layer 2 MP -> readout accumulation into repr
    fused_mp<<<dim3(4, BB), 128, FUSED_SMEM>>>(adj, yAh, yAl, ewh, ebs,
                                               lng + 2*HID, lnb + 2*HID,
                                               nwh, nwl, nb[0],
                                               yBh, yBl, repr, 1);
    out_gemv<<<BB, NOUT>>>(repr, oW, ob, (float*)d_out);
}